// round 10
// baseline (speedup 1.0000x reference)
#include <cuda_runtime.h>
#include <cuda_bf16.h>
#include <stdint.h>
#include <math.h>

#define BATCH 512
#define TSTEPS 32
#define BELIEF 1024
#define STATE 256
#define HIDDEN 1024
#define EMB 1024

#define BK 64
#define APAD 72
#define ROWB (APAD * 2)
#define NSTAGE 3

// ---------------- scratch ----------------------------------------------------
__device__ float g_gi[2 * BATCH * 3 * BELIEF];
__device__ float g_gh[2 * BATCH * 3 * BELIEF];
__device__ float g_ypo[2 * BATCH * 2 * STATE];
__device__ float g_ypr[2 * BATCH * 2 * STATE];

// split-bf16 activations: [R, 3L], sections [hi | lo | hi]
__device__ __align__(256) __nv_bfloat16 g_sb_state[BATCH * 3 * 512];
__device__ __align__(256) __nv_bfloat16 g_sb_hidden[BATCH * 3 * 1024];
__device__ __align__(256) __nv_bfloat16 g_sb_belief[BATCH * 3 * 1024];
__device__ __align__(256) __nv_bfloat16 g_sb_pose[BATCH * 3 * 64];
__device__ __align__(256) __nv_bfloat16 g_sb_hp[BATCH * 3 * 1024];
__device__ __align__(256) __nv_bfloat16 g_sb_hq[BATCH * 3 * 1024];
__device__ __align__(256) __nv_bfloat16 g_sb_obs[(size_t)TSTEPS * BATCH * 3 * 1024];

// split-bf16 weights [N, Kp=3L], sections [hi | hi | lo]
__device__ __align__(256) __nv_bfloat16 g_wb_es[1024 * 1536];
__device__ __align__(256) __nv_bfloat16 g_wb_ih[3072 * 3072];
__device__ __align__(256) __nv_bfloat16 g_wb_hh[3072 * 3072];
__device__ __align__(256) __nv_bfloat16 g_wb_ebpo[1024 * 6144];
__device__ __align__(256) __nv_bfloat16 g_wb_ebpr[1024 * 3264];
__device__ __align__(256) __nv_bfloat16 g_wb_spo[512 * 3072];
__device__ __align__(256) __nv_bfloat16 g_wb_spr[512 * 3072];

// ---------------- helpers ----------------------------------------------------
__device__ __forceinline__ uint32_t smem_u32(const void* p) {
    uint32_t a;
    asm("{ .reg .u64 t; cvta.to.shared.u64 t, %1; cvt.u32.u64 %0, t; }" : "=r"(a) : "l"(p));
    return a;
}
__device__ __forceinline__ void mma_bf16(float* c, const uint32_t* a, uint32_t b0, uint32_t b1) {
    asm volatile("mma.sync.aligned.m16n8k16.row.col.f32.bf16.bf16.f32 "
        "{%0,%1,%2,%3}, {%4,%5,%6,%7}, {%8,%9}, {%0,%1,%2,%3};"
        : "+f"(c[0]), "+f"(c[1]), "+f"(c[2]), "+f"(c[3])
        : "r"(a[0]), "r"(a[1]), "r"(a[2]), "r"(a[3]), "r"(b0), "r"(b1));
}

struct GemmP {
    const __nv_bfloat16* A0;
    const __nv_bfloat16* A1;
    const __nv_bfloat16* Wb;
    const float* bias;
    float* C;                       // f32 out / split-K partial base
    __nv_bfloat16* Csp;             // direct split-bf16 out
    int K1, K2, L, Kp, ldc, partStride, splits, gx, N;
};

// ---------------- tensor-core GEMM -------------------------------------------
// BMT in {64,128}; WN = cols per n-warp (32 -> BN=64, 64 -> BN=128).
// Up to 3 GEMMs co-launched via z ranges; blockIdx.x >= p.gx exits.
// F32OUT: write f32 (partial if splits>1). SPOUT: relu + split-bf16 direct.
template <int BMT, int WN, bool RELU, bool F32OUT, bool SPOUT>
__global__ __launch_bounds__(256, 2) void gemm_mma(GemmP pa, GemmP pb, GemmP pc,
                                                   int zb1, int zb2)
{
    constexpr int MF = BMT / 64;          // 16-row m-frags per warp
    constexpr int NB = WN / 16;           // x4-ldsm groups per n-warp
    constexpr int BN = 2 * WN;
    constexpr int ASZ = BMT * ROWB;
    constexpr int BSZ = BN * ROWB;
    extern __shared__ char smem[];
    const int z = blockIdx.z;
    GemmP p; int sidx;
    if (z < zb1)      { p = pa; sidx = z; }
    else if (z < zb2) { p = pb; sidx = z - zb1; }
    else              { p = pc; sidx = z - zb2; }
    if (blockIdx.x >= p.gx) return;

    const int nkt_all = p.Kp / BK;
    const int nbase = nkt_all / p.splits, nrem = nkt_all % p.splits;
    const int nkt = nbase + (sidx < nrem);
    const int kb = sidx * nbase + min(sidx, nrem);
    float* Cout = p.C + (size_t)sidx * p.partStride;
    const bool addBias = (sidx == 0);

    const int tid = threadIdx.x;
    const int wid = tid >> 5, lane = tid & 31;
    const int row0 = blockIdx.y * BMT, col0 = blockIdx.x * BN;
    const uint32_t sbase = smem_u32(smem);

    auto issue = [&](int i, int slot) {
        const int kp = i * BK;
        const int sec = (kp >= p.L) + (kp >= 2 * p.L);
        const int rb = kp - sec * p.L;
        const bool useA0 = (rb < p.K1);
        const __nv_bfloat16* abase = useA0
            ? (p.A0 + (size_t)row0 * (3 * p.K1) + sec * p.K1 + rb)
            : (p.A1 + (size_t)row0 * (3 * p.K2) + sec * p.K2 + (rb - p.K1));
        const int astr = useA0 ? 3 * p.K1 : 3 * p.K2;
        const uint32_t da = sbase + slot * ASZ;
        #pragma unroll
        for (int q = 0; q < BMT * 8 / 256; q++) {
            int idx = tid + q * 256;
            int r = idx >> 3, c = idx & 7;
            asm volatile("cp.async.cg.shared.global [%0], [%1], 16;"
                :: "r"(da + r * ROWB + c * 16), "l"(abase + (size_t)r * astr + c * 8));
        }
        const __nv_bfloat16* bbase = p.Wb + (size_t)col0 * p.Kp + i * BK;
        const uint32_t db = sbase + NSTAGE * ASZ + slot * BSZ;
        #pragma unroll
        for (int q = 0; q < BN * 8 / 256; q++) {
            int idx = tid + q * 256;
            int r = idx >> 3, c = idx & 7;
            asm volatile("cp.async.cg.shared.global [%0], [%1], 16;"
                :: "r"(db + r * ROWB + c * 16), "l"(bbase + (size_t)r * p.Kp + c * 8));
        }
        asm volatile("cp.async.commit_group;" ::: "memory");
    };

    const int wm = wid & 3, wn = wid >> 2;
    const uint32_t lrow = lane & 15;
    const uint32_t lk16 = (lane >> 4) * 16;

    float acc[MF][2 * NB][4];
    #pragma unroll
    for (int mf = 0; mf < MF; mf++)
        #pragma unroll
        for (int j = 0; j < 2 * NB; j++)
            #pragma unroll
            for (int q = 0; q < 4; q++) acc[mf][j][q] = 0.f;

    issue(kb + 0, 0);
    issue(kb + 1, 1);

    for (int it = 0; it < nkt; it++) {
        asm volatile("cp.async.wait_group 1;" ::: "memory");
        __syncthreads();
        const int slot = it % NSTAGE;
        const uint32_t aS = sbase + slot * ASZ + (wm * 16 * MF + lrow) * ROWB + lk16;
        const uint32_t bS = sbase + NSTAGE * ASZ + slot * BSZ + (wn * WN + lrow) * ROWB + lk16;
        #pragma unroll
        for (int ks = 0; ks < 4; ks++) {
            uint32_t a[MF][4];
            #pragma unroll
            for (int mf = 0; mf < MF; mf++)
                asm volatile("ldmatrix.sync.aligned.m8n8.x4.shared.b16 {%0,%1,%2,%3}, [%4];"
                    : "=r"(a[mf][0]), "=r"(a[mf][1]), "=r"(a[mf][2]), "=r"(a[mf][3])
                    : "r"(aS + mf * 16 * ROWB + ks * 32));
            #pragma unroll
            for (int nb = 0; nb < NB; nb++) {
                uint32_t b[4];
                asm volatile("ldmatrix.sync.aligned.m8n8.x4.shared.b16 {%0,%1,%2,%3}, [%4];"
                    : "=r"(b[0]), "=r"(b[1]), "=r"(b[2]), "=r"(b[3])
                    : "r"(bS + nb * 16 * ROWB + ks * 32));
                #pragma unroll
                for (int mf = 0; mf < MF; mf++) {
                    mma_bf16(acc[mf][2 * nb + 0], a[mf], b[0], b[2]);
                    mma_bf16(acc[mf][2 * nb + 1], a[mf], b[1], b[3]);
                }
            }
        }
        if (it + 2 < nkt) issue(kb + it + 2, (it + 2) % NSTAGE);
        else asm volatile("cp.async.commit_group;" ::: "memory");
    }

    // ---- epilogue ----
    #pragma unroll
    for (int mf = 0; mf < MF; mf++) {
        #pragma unroll
        for (int nf = 0; nf < 2 * NB; nf++) {
            const int row_ = row0 + wm * 16 * MF + mf * 16 + (lane >> 2);
            const int col_ = col0 + wn * WN + nf * 8 + (lane & 3) * 2;
            const float b0 = addBias ? p.bias[col_] : 0.f;
            const float b1 = addBias ? p.bias[col_ + 1] : 0.f;
            #pragma unroll
            for (int rh = 0; rh < 2; rh++) {
                float v0 = acc[mf][nf][rh * 2 + 0] + b0;
                float v1 = acc[mf][nf][rh * 2 + 1] + b1;
                if (RELU) { v0 = fmaxf(v0, 0.f); v1 = fmaxf(v1, 0.f); }
                const int rr = row_ + rh * 8;
                if (F32OUT)
                    *reinterpret_cast<float2*>(&Cout[(size_t)rr * p.ldc + col_]) = make_float2(v0, v1);
                if (SPOUT) {
                    __nv_bfloat16 h0 = __float2bfloat16(v0), h1 = __float2bfloat16(v1);
                    __nv_bfloat16 l0 = __float2bfloat16(v0 - __bfloat162float(h0));
                    __nv_bfloat16 l1 = __float2bfloat16(v1 - __bfloat162float(h1));
                    ushort2 hu; hu.x = __bfloat16_as_ushort(h0); hu.y = __bfloat16_as_ushort(h1);
                    ushort2 lu; lu.x = __bfloat16_as_ushort(l0); lu.y = __bfloat16_as_ushort(l1);
                    ushort* cs = reinterpret_cast<ushort*>(p.Csp);
                    const size_t base = (size_t)rr * 3 * p.N + col_;
                    *reinterpret_cast<ushort2*>(&cs[base]) = hu;
                    *reinterpret_cast<ushort2*>(&cs[base + p.N]) = lu;
                    *reinterpret_cast<ushort2*>(&cs[base + 2 * p.N]) = hu;
                }
            }
        }
    }
}

// ---------------- weight conversion -----------------------------------------
__global__ void convert_w(const float* __restrict__ W, int N, int Keff, int L,
                          int Kp, __nv_bfloat16* __restrict__ out)
{
    __shared__ unsigned short tile[32][33];
    int k0 = blockIdx.x * 32, n0 = blockIdx.y * 32;
    int tx = threadIdx.x, ty = threadIdx.y;
    #pragma unroll
    for (int q = 0; q < 4; q++) {
        int kl = ty + q * 8;
        int kp = k0 + kl;
        int s = kp / L;
        int rr = kp - s * L;
        float v = (rr < Keff) ? W[(size_t)rr * N + n0 + tx] : 0.f;
        __nv_bfloat16 b;
        if (s == 2) {
            __nv_bfloat16 h = __float2bfloat16(v);
            b = __float2bfloat16(v - __bfloat162float(h));
        } else b = __float2bfloat16(v);
        tile[kl][tx] = __bfloat16_as_ushort(b);
    }
    __syncthreads();
    #pragma unroll
    for (int q = 0; q < 4; q++) {
        int nl = ty + q * 8;
        reinterpret_cast<unsigned short*>(out)[(size_t)(n0 + nl) * Kp + k0 + tx] = tile[tx][nl];
    }
}

// ---------------- activation splits ------------------------------------------
__global__ void split_rows(const float* __restrict__ src, __nv_bfloat16* __restrict__ dst, int L)
{
    int r = blockIdx.y;
    int c = blockIdx.x * 256 + threadIdx.x;
    float v = src[(size_t)r * L + c];
    __nv_bfloat16 h = __float2bfloat16(v);
    __nv_bfloat16 l = __float2bfloat16(v - __bfloat162float(h));
    size_t o = (size_t)r * 3 * L + c;
    dst[o] = h; dst[o + L] = l; dst[o + 2 * L] = h;
}
__global__ void split_state0(const float* __restrict__ ps, __nv_bfloat16* __restrict__ dst)
{
    int idx = blockIdx.x * 256 + threadIdx.x;
    int b = idx >> 8, c = idx & 255;
    float v = ps[idx];
    __nv_bfloat16 h = __float2bfloat16(v);
    __nv_bfloat16 l = __float2bfloat16(v - __bfloat162float(h));
    size_t base = (size_t)b * 1536;
    dst[base + c] = h;        dst[base + 256 + c] = h;
    dst[base + 512 + c] = l;  dst[base + 768 + c] = l;
    dst[base + 1024 + c] = h; dst[base + 1280 + c] = h;
}

// ---------------- GRU gate (gi/gh: 2 partials each) --------------------------
__device__ __forceinline__ float sigmoidf_(float x) { return 1.f / (1.f + expf(-x)); }
#define PS3 (512 * 3072)

__global__ void gru_gate(const float* __restrict__ gi, const float* __restrict__ gh,
                         const float* __restrict__ hprev, const float* __restrict__ pose_t,
                         float* __restrict__ belief_out,
                         __nv_bfloat16* __restrict__ sb_belief,
                         __nv_bfloat16* __restrict__ sb_pose)
{
    int idx = blockIdx.x * blockDim.x + threadIdx.x;
    int b = idx >> 10;
    int j = idx & 1023;
    size_t base = (size_t)b * 3072;
    float ir = gi[base + j] + gi[PS3 + base + j];
    float iz = gi[base + 1024 + j] + gi[PS3 + base + 1024 + j];
    float in_ = gi[base + 2048 + j] + gi[PS3 + base + 2048 + j];
    float hr = gh[base + j] + gh[PS3 + base + j];
    float hz = gh[base + 1024 + j] + gh[PS3 + base + 1024 + j];
    float hn = gh[base + 2048 + j] + gh[PS3 + base + 2048 + j];
    float rg = sigmoidf_(ir + hr);
    float zg = sigmoidf_(iz + hz);
    float n = tanhf(in_ + rg * hn);
    float h = hprev[(size_t)b * 1024 + j];
    float hv = (1.f - zg) * n + zg * h;
    belief_out[(size_t)b * 1024 + j] = hv;
    __nv_bfloat16 bh = __float2bfloat16(hv);
    __nv_bfloat16 bl = __float2bfloat16(hv - __bfloat162float(bh));
    sb_belief[base + j] = bh;
    sb_belief[base + 1024 + j] = bl;
    sb_belief[base + 2048 + j] = bh;
    if (j < 6) {
        float pv = pose_t[b * 6 + j];
        __nv_bfloat16 ph = __float2bfloat16(pv);
        __nv_bfloat16 pl = __float2bfloat16(pv - __bfloat162float(ph));
        size_t pb = (size_t)b * 192;
        sb_pose[pb + j] = ph;
        sb_pose[pb + 64 + j] = pl;
        sb_pose[pb + 128 + j] = ph;
    }
}

// ---------------- merged dist heads (sums 2 split-K partials) ----------------
#define PSH (512 * 512)
__global__ void dist_head2(const float* __restrict__ ypo, const float* __restrict__ ypr,
                           const float* __restrict__ pn, const float* __restrict__ rn,
                           float* __restrict__ pm, float* __restrict__ psd, float* __restrict__ ps,
                           float* __restrict__ prm, float* __restrict__ prsd, float* __restrict__ prs,
                           __nv_bfloat16* __restrict__ sb_state)
{
    int i2 = blockIdx.x * 256 + threadIdx.x;
    int half = i2 >> 17;
    int idx = i2 & 131071;
    int b = idx >> 8, c = idx & 255;
    const float* y = half ? ypr : ypo;
    const float* nz = half ? rn : pn;
    size_t bm = (size_t)b * 512 + c;
    size_t br = bm + 256;
    float m = y[bm] + y[PSH + bm];
    float raw = y[br] + y[PSH + br];
    float sd = fmaxf(raw, 0.f) + log1pf(expf(-fabsf(raw))) + 0.1f;
    float st = m + sd * nz[idx];
    if (half) { prm[idx] = m; prsd[idx] = sd; prs[idx] = st; }
    else      { pm[idx] = m;  psd[idx] = sd;  ps[idx] = st; }
    __nv_bfloat16 h = __float2bfloat16(st);
    __nv_bfloat16 l = __float2bfloat16(st - __bfloat162float(h));
    int off = half ? 256 : 0;
    size_t base = (size_t)b * 1536 + off + c;
    sb_state[base] = h;
    sb_state[base + 512] = l;
    sb_state[base + 1024] = h;
}

// ---------------- launch ------------------------------------------------------
extern "C" void kernel_launch(void* const* d_in, const int* in_sizes, int n_in,
                              void* d_out, int out_size)
{
    const float* prev_state   = (const float*)d_in[0];
    const float* prev_belief  = (const float*)d_in[1];
    const float* poses        = (const float*)d_in[2];
    const float* observations = (const float*)d_in[3];
    const float* post_noise   = (const float*)d_in[4];
    const float* prior_noise  = (const float*)d_in[5];
    const float* w_es   = (const float*)d_in[6];
    const float* b_es   = (const float*)d_in[7];
    const float* w_ih   = (const float*)d_in[8];
    const float* w_hh   = (const float*)d_in[9];
    const float* b_ih   = (const float*)d_in[10];
    const float* b_hh   = (const float*)d_in[11];
    const float* w_ebpo = (const float*)d_in[12];
    const float* b_ebpo = (const float*)d_in[13];
    const float* w_spo  = (const float*)d_in[14];
    const float* b_spo  = (const float*)d_in[15];
    const float* w_ebpr = (const float*)d_in[16];
    const float* b_ebpr = (const float*)d_in[17];
    const float* w_spr  = (const float*)d_in[18];
    const float* b_spr  = (const float*)d_in[19];

    float* out = (float*)d_out;
    const size_t SZB = (size_t)TSTEPS * BATCH * BELIEF;
    const size_t SZS = (size_t)TSTEPS * BATCH * STATE;
    float* out_belief = out;
    float* out_prs  = out + SZB;
    float* out_prm  = out + SZB + 1 * SZS;
    float* out_prsd = out + SZB + 2 * SZS;
    float* out_ps   = out + SZB + 3 * SZS;
    float* out_pm   = out + SZB + 4 * SZS;
    float* out_psd  = out + SZB + 5 * SZS;

    float *gi, *gh, *ypo, *ypr;
    cudaGetSymbolAddress((void**)&gi, g_gi);
    cudaGetSymbolAddress((void**)&gh, g_gh);
    cudaGetSymbolAddress((void**)&ypo, g_ypo);
    cudaGetSymbolAddress((void**)&ypr, g_ypr);

    __nv_bfloat16 *sb_state, *sb_hidden, *sb_belief, *sb_pose, *sb_hp, *sb_hq, *sb_obs;
    cudaGetSymbolAddress((void**)&sb_state, g_sb_state);
    cudaGetSymbolAddress((void**)&sb_hidden, g_sb_hidden);
    cudaGetSymbolAddress((void**)&sb_belief, g_sb_belief);
    cudaGetSymbolAddress((void**)&sb_pose, g_sb_pose);
    cudaGetSymbolAddress((void**)&sb_hp, g_sb_hp);
    cudaGetSymbolAddress((void**)&sb_hq, g_sb_hq);
    cudaGetSymbolAddress((void**)&sb_obs, g_sb_obs);

    __nv_bfloat16 *wb_es, *wb_ih, *wb_hh, *wb_ebpo, *wb_ebpr, *wb_spo, *wb_spr;
    cudaGetSymbolAddress((void**)&wb_es, g_wb_es);
    cudaGetSymbolAddress((void**)&wb_ih, g_wb_ih);
    cudaGetSymbolAddress((void**)&wb_hh, g_wb_hh);
    cudaGetSymbolAddress((void**)&wb_ebpo, g_wb_ebpo);
    cudaGetSymbolAddress((void**)&wb_ebpr, g_wb_ebpr);
    cudaGetSymbolAddress((void**)&wb_spo, g_wb_spo);
    cudaGetSymbolAddress((void**)&wb_spr, g_wb_spr);

    const int SM6464   = NSTAGE * (64 + 64) * ROWB;     // 55296
    const int SM128128 = NSTAGE * (128 + 128) * ROWB;   // 110592
    cudaFuncSetAttribute((const void*)gemm_mma<64, 32, true, false, true>,
                         cudaFuncAttributeMaxDynamicSharedMemorySize, SM6464);
    cudaFuncSetAttribute((const void*)gemm_mma<64, 32, false, true, false>,
                         cudaFuncAttributeMaxDynamicSharedMemorySize, SM6464);
    cudaFuncSetAttribute((const void*)gemm_mma<128, 64, false, true, false>,
                         cudaFuncAttributeMaxDynamicSharedMemorySize, SM128128);

    // ---- upfront conversions ----
    dim3 cblk(32, 8);
    convert_w<<<dim3(48, 32), cblk>>>(w_es,   1024, 512,  512,  1536, wb_es);
    convert_w<<<dim3(96, 96), cblk>>>(w_ih,   3072, 1024, 1024, 3072, wb_ih);
    convert_w<<<dim3(96, 96), cblk>>>(w_hh,   3072, 1024, 1024, 3072, wb_hh);
    convert_w<<<dim3(192, 32), cblk>>>(w_ebpo, 1024, 2048, 2048, 6144, wb_ebpo);
    convert_w<<<dim3(102, 32), cblk>>>(w_ebpr, 1024, 1030, 1088, 3264, wb_ebpr);
    convert_w<<<dim3(96, 16), cblk>>>(w_spo,  512,  1024, 1024, 3072, wb_spo);
    convert_w<<<dim3(96, 16), cblk>>>(w_spr,  512,  1024, 1024, 3072, wb_spr);
    split_rows<<<dim3(4, TSTEPS * BATCH), 256>>>(observations, sb_obs, 1024);
    split_rows<<<dim3(4, BATCH), 256>>>(prev_belief, sb_belief, 1024);
    split_state0<<<512, 256>>>(prev_state, sb_state);

    // ---- GEMM params:               A0        A1        Wb       bias    C     Csp        K1    K2    L     Kp    ldc   partStride  splits gx  N
    GemmP pes  = { sb_state,  nullptr, wb_es,   b_es,   nullptr, sb_hidden, 512,  0,    512,  1536, 0,    0,          1, 16, 1024 };
    GemmP pgi  = { sb_hidden, nullptr, wb_ih,   b_ih,   gi,      nullptr,   1024, 0,    1024, 3072, 3072, 512 * 3072, 2, 24, 3072 };
    GemmP pgh  = { sb_belief, nullptr, wb_hh,   b_hh,   gh,      nullptr,   1024, 0,    1024, 3072, 3072, 512 * 3072, 2, 24, 3072 };
    GemmP pep  = { sb_belief, nullptr, wb_ebpo, b_ebpo, nullptr, sb_hp,     1024, 1024, 2048, 6144, 0,    0,          1, 16, 1024 };
    GemmP peq  = { sb_belief, sb_pose, wb_ebpr, b_ebpr, nullptr, sb_hq,     1024, 64,   1088, 3264, 0,    0,          1, 16, 1024 };
    GemmP pso  = { sb_hp,     nullptr, wb_spo,  b_spo,  ypo,     nullptr,   1024, 0,    1024, 3072, 512,  512 * 512,  2, 8,  512 };
    GemmP psr  = { sb_hq,     nullptr, wb_spr,  b_spr,  ypr,     nullptr,   1024, 0,    1024, 3072, 512,  512 * 512,  2, 8,  512 };

    for (int t = 0; t < TSTEPS; t++) {
        const float* belief_p = (t == 0) ? prev_belief : out_belief + (size_t)(t - 1) * BATCH * BELIEF;
        float* belief_t = out_belief + (size_t)t * BATCH * BELIEF;
        const float* pose_t = poses + (size_t)t * BATCH * 6;
        pep.A1 = sb_obs + (size_t)t * BATCH * 3072;

        // 1: es -> sb_hidden directly (BN64, S=1, fused relu+split)
        gemm_mma<64, 32, true, false, true><<<dim3(16, 8, 1), 256, SM6464>>>(pes, pes, pes, 1, 1);
        // 2: gi + gh pair (BM128/BN128, S=2 each)
        gemm_mma<128, 64, false, true, false><<<dim3(24, 4, 4), 256, SM128128>>>(pgi, pgh, pgh, 2, 4);
        // 3: GRU
        gru_gate<<<2048, 256>>>(gi, gh, belief_p, pose_t, belief_t, sb_belief, sb_pose);
        // 4: pep + peq -> sb_hp/sb_hq directly (BN64, S=1, fused relu+split)
        gemm_mma<64, 32, true, false, true><<<dim3(16, 8, 2), 256, SM6464>>>(pep, peq, peq, 1, 2);
        // 5: pso + psr (BN64, S=2 partial)
        gemm_mma<64, 32, false, true, false><<<dim3(8, 8, 4), 256, SM6464>>>(pso, psr, psr, 2, 4);
        // 6: dist heads
        dist_head2<<<1024, 256>>>(ypo, ypr,
                                  post_noise + (size_t)t * BATCH * STATE,
                                  prior_noise + (size_t)t * BATCH * STATE,
                                  out_pm  + (size_t)t * BATCH * STATE,
                                  out_psd + (size_t)t * BATCH * STATE,
                                  out_ps  + (size_t)t * BATCH * STATE,
                                  out_prm  + (size_t)t * BATCH * STATE,
                                  out_prsd + (size_t)t * BATCH * STATE,
                                  out_prs  + (size_t)t * BATCH * STATE,
                                  sb_state);
    }
}

// round 11
// speedup vs baseline: 1.1460x; 1.1460x over previous
#include <cuda_runtime.h>
#include <cuda_bf16.h>
#include <stdint.h>
#include <math.h>

#define BATCH 512
#define TSTEPS 32
#define BELIEF 1024
#define STATE 256
#define HIDDEN 1024
#define EMB 1024

#define BK 64
#define BN 128
#define APAD 72
#define ROWB (APAD * 2)
#define NSTAGE 3

// ---------------- scratch ----------------------------------------------------
__device__ float g_gi[3 * BATCH * 3 * BELIEF];
__device__ float g_gh[3 * BATCH * 3 * BELIEF];
__device__ float g_hid_p[4 * BATCH * BELIEF];
__device__ float g_hp_p[2 * BATCH * HIDDEN];
__device__ float g_hq_p[2 * BATCH * HIDDEN];
__device__ float g_ypo[4 * BATCH * 2 * STATE];
__device__ float g_ypr[4 * BATCH * 2 * STATE];

// split-bf16 activations: [R, 3L], sections [hi | lo | hi]
__device__ __align__(256) __nv_bfloat16 g_sb_state[BATCH * 3 * 512];
__device__ __align__(256) __nv_bfloat16 g_sb_hidden[BATCH * 3 * 1024];
__device__ __align__(256) __nv_bfloat16 g_sb_belief[BATCH * 3 * 1024];
__device__ __align__(256) __nv_bfloat16 g_sb_pose[BATCH * 3 * 64];
__device__ __align__(256) __nv_bfloat16 g_sb_hp[BATCH * 3 * 1024];
__device__ __align__(256) __nv_bfloat16 g_sb_hq[BATCH * 3 * 1024];
__device__ __align__(256) __nv_bfloat16 g_sb_obs[(size_t)TSTEPS * BATCH * 3 * 1024];

// split-bf16 weights [N, Kp=3L], sections [hi | hi | lo]
__device__ __align__(256) __nv_bfloat16 g_wb_es[1024 * 1536];
__device__ __align__(256) __nv_bfloat16 g_wb_ih[3072 * 3072];
__device__ __align__(256) __nv_bfloat16 g_wb_hh[3072 * 3072];
__device__ __align__(256) __nv_bfloat16 g_wb_ebpo[1024 * 6144];
__device__ __align__(256) __nv_bfloat16 g_wb_ebpr[1024 * 3264];
__device__ __align__(256) __nv_bfloat16 g_wb_spo[512 * 3072];
__device__ __align__(256) __nv_bfloat16 g_wb_spr[512 * 3072];

// ---------------- helpers ----------------------------------------------------
__device__ __forceinline__ uint32_t smem_u32(const void* p) {
    uint32_t a;
    asm("{ .reg .u64 t; cvta.to.shared.u64 t, %1; cvt.u32.u64 %0, t; }" : "=r"(a) : "l"(p));
    return a;
}
__device__ __forceinline__ void mma_bf16(float* c, const uint32_t* a, uint32_t b0, uint32_t b1) {
    asm volatile("mma.sync.aligned.m16n8k16.row.col.f32.bf16.bf16.f32 "
        "{%0,%1,%2,%3}, {%4,%5,%6,%7}, {%8,%9}, {%0,%1,%2,%3};"
        : "+f"(c[0]), "+f"(c[1]), "+f"(c[2]), "+f"(c[3])
        : "r"(a[0]), "r"(a[1]), "r"(a[2]), "r"(a[3]), "r"(b0), "r"(b1));
}

struct GemmP {
    const __nv_bfloat16* A0;
    const __nv_bfloat16* A1;
    const __nv_bfloat16* Wb;
    const float* bias;
    float* C;                       // partial base; split s writes C + s*partStride
    int K1, K2, L, Kp, ldc, partStride;
};

// ---------------- tensor-core GEMM (pure f32-partial, split-K') --------------
// blockIdx.z = gemm_idx * SPLITS + split_idx
template <int BMT, int SPLITS>
__global__ __launch_bounds__(256, 2) void gemm_mma(GemmP p0, GemmP p1)
{
    constexpr int MF = BMT / 64;
    constexpr int ASZ = BMT * ROWB;
    constexpr int BSZ = BN * ROWB;
    extern __shared__ char smem[];
    const int z = blockIdx.z;
    const int gidx = z / SPLITS, sidx = z % SPLITS;
    const GemmP p = gidx ? p1 : p0;
    const int nkt_all = p.Kp / BK;
    const int nbase = nkt_all / SPLITS, nrem = nkt_all % SPLITS;
    const int nkt = nbase + (sidx < nrem);
    const int kb = sidx * nbase + min(sidx, nrem);
    float* Cout = p.C + (size_t)sidx * p.partStride;
    const bool addBias = (sidx == 0);

    const int tid = threadIdx.x;
    const int wid = tid >> 5, lane = tid & 31;
    const int row0 = blockIdx.y * BMT, col0 = blockIdx.x * BN;
    const uint32_t sbase = smem_u32(smem);

    auto issue = [&](int i, int slot) {
        const int kp = i * BK;
        const int sec = (kp >= p.L) + (kp >= 2 * p.L);
        const int rb = kp - sec * p.L;
        const bool useA0 = (rb < p.K1);
        const __nv_bfloat16* abase = useA0
            ? (p.A0 + (size_t)row0 * (3 * p.K1) + sec * p.K1 + rb)
            : (p.A1 + (size_t)row0 * (3 * p.K2) + sec * p.K2 + (rb - p.K1));
        const int astr = useA0 ? 3 * p.K1 : 3 * p.K2;
        const uint32_t da = sbase + slot * ASZ;
        #pragma unroll
        for (int q = 0; q < BMT * 8 / 256; q++) {
            int idx = tid + q * 256;
            int r = idx >> 3, c = idx & 7;
            asm volatile("cp.async.cg.shared.global [%0], [%1], 16;"
                :: "r"(da + r * ROWB + c * 16), "l"(abase + (size_t)r * astr + c * 8));
        }
        const __nv_bfloat16* bbase = p.Wb + (size_t)col0 * p.Kp + i * BK;
        const uint32_t db = sbase + NSTAGE * ASZ + slot * BSZ;
        #pragma unroll
        for (int q = 0; q < BN * 8 / 256; q++) {
            int idx = tid + q * 256;
            int r = idx >> 3, c = idx & 7;
            asm volatile("cp.async.cg.shared.global [%0], [%1], 16;"
                :: "r"(db + r * ROWB + c * 16), "l"(bbase + (size_t)r * p.Kp + c * 8));
        }
        asm volatile("cp.async.commit_group;" ::: "memory");
    };

    const int wm = wid & 3, wn = wid >> 2;
    const uint32_t lrow = lane & 15;
    const uint32_t lk16 = (lane >> 4) * 16;

    float acc[MF][8][4];
    #pragma unroll
    for (int mf = 0; mf < MF; mf++)
        #pragma unroll
        for (int j = 0; j < 8; j++)
            #pragma unroll
            for (int q = 0; q < 4; q++) acc[mf][j][q] = 0.f;

    issue(kb + 0, 0);
    issue(kb + 1, 1);

    for (int it = 0; it < nkt; it++) {
        asm volatile("cp.async.wait_group 1;" ::: "memory");
        __syncthreads();
        const int slot = it % NSTAGE;
        const uint32_t aS = sbase + slot * ASZ + (wm * 16 * MF + lrow) * ROWB + lk16;
        const uint32_t bS = sbase + NSTAGE * ASZ + slot * BSZ + (wn * 64 + lrow) * ROWB + lk16;
        #pragma unroll
        for (int ks = 0; ks < 4; ks++) {
            uint32_t a[MF][4];
            #pragma unroll
            for (int mf = 0; mf < MF; mf++)
                asm volatile("ldmatrix.sync.aligned.m8n8.x4.shared.b16 {%0,%1,%2,%3}, [%4];"
                    : "=r"(a[mf][0]), "=r"(a[mf][1]), "=r"(a[mf][2]), "=r"(a[mf][3])
                    : "r"(aS + mf * 16 * ROWB + ks * 32));
            #pragma unroll
            for (int nb = 0; nb < 4; nb++) {
                uint32_t b[4];
                asm volatile("ldmatrix.sync.aligned.m8n8.x4.shared.b16 {%0,%1,%2,%3}, [%4];"
                    : "=r"(b[0]), "=r"(b[1]), "=r"(b[2]), "=r"(b[3])
                    : "r"(bS + nb * 16 * ROWB + ks * 32));
                #pragma unroll
                for (int mf = 0; mf < MF; mf++) {
                    mma_bf16(acc[mf][2 * nb + 0], a[mf], b[0], b[2]);
                    mma_bf16(acc[mf][2 * nb + 1], a[mf], b[1], b[3]);
                }
            }
        }
        if (it + 2 < nkt) issue(kb + it + 2, (it + 2) % NSTAGE);
        else asm volatile("cp.async.commit_group;" ::: "memory");
    }

    #pragma unroll
    for (int mf = 0; mf < MF; mf++) {
        #pragma unroll
        for (int nf = 0; nf < 8; nf++) {
            const int row_ = row0 + wm * 16 * MF + mf * 16 + (lane >> 2);
            const int col_ = col0 + wn * 64 + nf * 8 + (lane & 3) * 2;
            const float b0 = addBias ? p.bias[col_] : 0.f;
            const float b1 = addBias ? p.bias[col_ + 1] : 0.f;
            #pragma unroll
            for (int rh = 0; rh < 2; rh++) {
                float v0 = acc[mf][nf][rh * 2 + 0] + b0;
                float v1 = acc[mf][nf][rh * 2 + 1] + b1;
                const int rr = row_ + rh * 8;
                *reinterpret_cast<float2*>(&Cout[(size_t)rr * p.ldc + col_]) = make_float2(v0, v1);
            }
        }
    }
}

// ---------------- weight conversion -----------------------------------------
__global__ void convert_w(const float* __restrict__ W, int N, int Keff, int L,
                          int Kp, __nv_bfloat16* __restrict__ out)
{
    __shared__ unsigned short tile[32][33];
    int k0 = blockIdx.x * 32, n0 = blockIdx.y * 32;
    int tx = threadIdx.x, ty = threadIdx.y;
    #pragma unroll
    for (int q = 0; q < 4; q++) {
        int kl = ty + q * 8;
        int kp = k0 + kl;
        int s = kp / L;
        int rr = kp - s * L;
        float v = (rr < Keff) ? W[(size_t)rr * N + n0 + tx] : 0.f;
        __nv_bfloat16 b;
        if (s == 2) {
            __nv_bfloat16 h = __float2bfloat16(v);
            b = __float2bfloat16(v - __bfloat162float(h));
        } else b = __float2bfloat16(v);
        tile[kl][tx] = __bfloat16_as_ushort(b);
    }
    __syncthreads();
    #pragma unroll
    for (int q = 0; q < 4; q++) {
        int nl = ty + q * 8;
        reinterpret_cast<unsigned short*>(out)[(size_t)(n0 + nl) * Kp + k0 + tx] = tile[tx][nl];
    }
}

// ---------------- activation splits ------------------------------------------
__global__ void split_rows(const float* __restrict__ src, __nv_bfloat16* __restrict__ dst, int L)
{
    int r = blockIdx.y;
    int c = blockIdx.x * 256 + threadIdx.x;
    float v = src[(size_t)r * L + c];
    __nv_bfloat16 h = __float2bfloat16(v);
    __nv_bfloat16 l = __float2bfloat16(v - __bfloat162float(h));
    size_t o = (size_t)r * 3 * L + c;
    dst[o] = h; dst[o + L] = l; dst[o + 2 * L] = h;
}
__global__ void split_state0(const float* __restrict__ ps, __nv_bfloat16* __restrict__ dst)
{
    int idx = blockIdx.x * 256 + threadIdx.x;
    int b = idx >> 8, c = idx & 255;
    float v = ps[idx];
    __nv_bfloat16 h = __float2bfloat16(v);
    __nv_bfloat16 l = __float2bfloat16(v - __bfloat162float(h));
    size_t base = (size_t)b * 1536;
    dst[base + c] = h;        dst[base + 256 + c] = h;
    dst[base + 512 + c] = l;  dst[base + 768 + c] = l;
    dst[base + 1024 + c] = h; dst[base + 1280 + c] = h;
}

// ---------------- reduce + relu + split --------------------------------------
__global__ void rrs1(const float* __restrict__ part, __nv_bfloat16* __restrict__ dst, int nsplit)
{
    int idx = blockIdx.x * 256 + threadIdx.x;          // 512*1024
    int r = idx >> 10, c = idx & 1023;
    float v = 0.f;
    for (int s = 0; s < nsplit; s++) v += part[idx + (size_t)s * 512 * 1024];
    v = fmaxf(v, 0.f);
    __nv_bfloat16 h = __float2bfloat16(v);
    __nv_bfloat16 l = __float2bfloat16(v - __bfloat162float(h));
    size_t o = (size_t)r * 3072 + c;
    dst[o] = h; dst[o + 1024] = l; dst[o + 2048] = h;
}
__global__ void rrs2(const float* __restrict__ pa, const float* __restrict__ pb,
                     __nv_bfloat16* __restrict__ da, __nv_bfloat16* __restrict__ db)
{
    int i2 = blockIdx.x * 256 + threadIdx.x;           // 2*512*1024
    int half = i2 >> 19;
    int idx = i2 & 524287;
    const float* part = half ? pb : pa;
    __nv_bfloat16* dst = half ? db : da;
    int r = idx >> 10, c = idx & 1023;
    float v = part[idx] + part[idx + 512 * 1024];
    v = fmaxf(v, 0.f);
    __nv_bfloat16 h = __float2bfloat16(v);
    __nv_bfloat16 l = __float2bfloat16(v - __bfloat162float(h));
    size_t o = (size_t)r * 3072 + c;
    dst[o] = h; dst[o + 1024] = l; dst[o + 2048] = h;
}

// ---------------- GRU gate (gi: 3 partials, gh: 3 partials) -----------------
__device__ __forceinline__ float sigmoidf_(float x) { return 1.f / (1.f + expf(-x)); }
#define PS3 (512 * 3072)

__global__ void gru_gate(const float* __restrict__ gi, const float* __restrict__ gh,
                         const float* __restrict__ hprev, const float* __restrict__ pose_t,
                         float* __restrict__ belief_out,
                         __nv_bfloat16* __restrict__ sb_belief,
                         __nv_bfloat16* __restrict__ sb_pose)
{
    int idx = blockIdx.x * blockDim.x + threadIdx.x;
    int b = idx >> 10;
    int j = idx & 1023;
    size_t base = (size_t)b * 3072;
    float ir = gi[base + j] + gi[PS3 + base + j] + gi[2 * PS3 + base + j];
    float iz = gi[base + 1024 + j] + gi[PS3 + base + 1024 + j] + gi[2 * PS3 + base + 1024 + j];
    float in_ = gi[base + 2048 + j] + gi[PS3 + base + 2048 + j] + gi[2 * PS3 + base + 2048 + j];
    float hr = gh[base + j] + gh[PS3 + base + j] + gh[2 * PS3 + base + j];
    float hz = gh[base + 1024 + j] + gh[PS3 + base + 1024 + j] + gh[2 * PS3 + base + 1024 + j];
    float hn = gh[base + 2048 + j] + gh[PS3 + base + 2048 + j] + gh[2 * PS3 + base + 2048 + j];
    float rg = sigmoidf_(ir + hr);
    float zg = sigmoidf_(iz + hz);
    float n = tanhf(in_ + rg * hn);
    float h = hprev[(size_t)b * 1024 + j];
    float hv = (1.f - zg) * n + zg * h;
    belief_out[(size_t)b * 1024 + j] = hv;
    __nv_bfloat16 bh = __float2bfloat16(hv);
    __nv_bfloat16 bl = __float2bfloat16(hv - __bfloat162float(bh));
    sb_belief[base + j] = bh;
    sb_belief[base + 1024 + j] = bl;
    sb_belief[base + 2048 + j] = bh;
    if (j < 6) {
        float pv = pose_t[b * 6 + j];
        __nv_bfloat16 ph = __float2bfloat16(pv);
        __nv_bfloat16 pl = __float2bfloat16(pv - __bfloat162float(ph));
        size_t pb = (size_t)b * 192;
        sb_pose[pb + j] = ph;
        sb_pose[pb + 64 + j] = pl;
        sb_pose[pb + 128 + j] = ph;
    }
}

// ---------------- merged dist heads (sums 4 split-K partials) ----------------
#define PSH (512 * 512)
__global__ void dist_head2(const float* __restrict__ ypo, const float* __restrict__ ypr,
                           const float* __restrict__ pn, const float* __restrict__ rn,
                           float* __restrict__ pm, float* __restrict__ psd, float* __restrict__ ps,
                           float* __restrict__ prm, float* __restrict__ prsd, float* __restrict__ prs,
                           __nv_bfloat16* __restrict__ sb_state)
{
    int i2 = blockIdx.x * 256 + threadIdx.x;
    int half = i2 >> 17;
    int idx = i2 & 131071;
    int b = idx >> 8, c = idx & 255;
    const float* y = half ? ypr : ypo;
    const float* nz = half ? rn : pn;
    size_t bm = (size_t)b * 512 + c;
    size_t br = bm + 256;
    float m = y[bm] + y[PSH + bm] + y[2 * PSH + bm] + y[3 * PSH + bm];
    float raw = y[br] + y[PSH + br] + y[2 * PSH + br] + y[3 * PSH + br];
    float sd = fmaxf(raw, 0.f) + log1pf(expf(-fabsf(raw))) + 0.1f;
    float st = m + sd * nz[idx];
    if (half) { prm[idx] = m; prsd[idx] = sd; prs[idx] = st; }
    else      { pm[idx] = m;  psd[idx] = sd;  ps[idx] = st; }
    __nv_bfloat16 h = __float2bfloat16(st);
    __nv_bfloat16 l = __float2bfloat16(st - __bfloat162float(h));
    int off = half ? 256 : 0;
    size_t base = (size_t)b * 1536 + off + c;
    sb_state[base] = h;
    sb_state[base + 512] = l;
    sb_state[base + 1024] = h;
}

// ---------------- launch ------------------------------------------------------
extern "C" void kernel_launch(void* const* d_in, const int* in_sizes, int n_in,
                              void* d_out, int out_size)
{
    const float* prev_state   = (const float*)d_in[0];
    const float* prev_belief  = (const float*)d_in[1];
    const float* poses        = (const float*)d_in[2];
    const float* observations = (const float*)d_in[3];
    const float* post_noise   = (const float*)d_in[4];
    const float* prior_noise  = (const float*)d_in[5];
    const float* w_es   = (const float*)d_in[6];
    const float* b_es   = (const float*)d_in[7];
    const float* w_ih   = (const float*)d_in[8];
    const float* w_hh   = (const float*)d_in[9];
    const float* b_ih   = (const float*)d_in[10];
    const float* b_hh   = (const float*)d_in[11];
    const float* w_ebpo = (const float*)d_in[12];
    const float* b_ebpo = (const float*)d_in[13];
    const float* w_spo  = (const float*)d_in[14];
    const float* b_spo  = (const float*)d_in[15];
    const float* w_ebpr = (const float*)d_in[16];
    const float* b_ebpr = (const float*)d_in[17];
    const float* w_spr  = (const float*)d_in[18];
    const float* b_spr  = (const float*)d_in[19];

    float* out = (float*)d_out;
    const size_t SZB = (size_t)TSTEPS * BATCH * BELIEF;
    const size_t SZS = (size_t)TSTEPS * BATCH * STATE;
    float* out_belief = out;
    float* out_prs  = out + SZB;
    float* out_prm  = out + SZB + 1 * SZS;
    float* out_prsd = out + SZB + 2 * SZS;
    float* out_ps   = out + SZB + 3 * SZS;
    float* out_pm   = out + SZB + 4 * SZS;
    float* out_psd  = out + SZB + 5 * SZS;

    float *gi, *gh, *hid_p, *hp_p, *hq_p, *ypo, *ypr;
    cudaGetSymbolAddress((void**)&gi, g_gi);
    cudaGetSymbolAddress((void**)&gh, g_gh);
    cudaGetSymbolAddress((void**)&hid_p, g_hid_p);
    cudaGetSymbolAddress((void**)&hp_p, g_hp_p);
    cudaGetSymbolAddress((void**)&hq_p, g_hq_p);
    cudaGetSymbolAddress((void**)&ypo, g_ypo);
    cudaGetSymbolAddress((void**)&ypr, g_ypr);

    __nv_bfloat16 *sb_state, *sb_hidden, *sb_belief, *sb_pose, *sb_hp, *sb_hq, *sb_obs;
    cudaGetSymbolAddress((void**)&sb_state, g_sb_state);
    cudaGetSymbolAddress((void**)&sb_hidden, g_sb_hidden);
    cudaGetSymbolAddress((void**)&sb_belief, g_sb_belief);
    cudaGetSymbolAddress((void**)&sb_pose, g_sb_pose);
    cudaGetSymbolAddress((void**)&sb_hp, g_sb_hp);
    cudaGetSymbolAddress((void**)&sb_hq, g_sb_hq);
    cudaGetSymbolAddress((void**)&sb_obs, g_sb_obs);

    __nv_bfloat16 *wb_es, *wb_ih, *wb_hh, *wb_ebpo, *wb_ebpr, *wb_spo, *wb_spr;
    cudaGetSymbolAddress((void**)&wb_es, g_wb_es);
    cudaGetSymbolAddress((void**)&wb_ih, g_wb_ih);
    cudaGetSymbolAddress((void**)&wb_hh, g_wb_hh);
    cudaGetSymbolAddress((void**)&wb_ebpo, g_wb_ebpo);
    cudaGetSymbolAddress((void**)&wb_ebpr, g_wb_ebpr);
    cudaGetSymbolAddress((void**)&wb_spo, g_wb_spo);
    cudaGetSymbolAddress((void**)&wb_spr, g_wb_spr);

    const int SM64  = NSTAGE * (64 + BN) * ROWB;    // 82944
    const int SM128 = NSTAGE * (128 + BN) * ROWB;   // 110592
    cudaFuncSetAttribute((const void*)gemm_mma<64, 2>,
                         cudaFuncAttributeMaxDynamicSharedMemorySize, SM64);
    cudaFuncSetAttribute((const void*)gemm_mma<64, 4>,
                         cudaFuncAttributeMaxDynamicSharedMemorySize, SM64);
    cudaFuncSetAttribute((const void*)gemm_mma<128, 3>,
                         cudaFuncAttributeMaxDynamicSharedMemorySize, SM128);

    // ---- upfront conversions ----
    dim3 cblk(32, 8);
    convert_w<<<dim3(48, 32), cblk>>>(w_es,   1024, 512,  512,  1536, wb_es);
    convert_w<<<dim3(96, 96), cblk>>>(w_ih,   3072, 1024, 1024, 3072, wb_ih);
    convert_w<<<dim3(96, 96), cblk>>>(w_hh,   3072, 1024, 1024, 3072, wb_hh);
    convert_w<<<dim3(192, 32), cblk>>>(w_ebpo, 1024, 2048, 2048, 6144, wb_ebpo);
    convert_w<<<dim3(102, 32), cblk>>>(w_ebpr, 1024, 1030, 1088, 3264, wb_ebpr);
    convert_w<<<dim3(96, 16), cblk>>>(w_spo,  512,  1024, 1024, 3072, wb_spo);
    convert_w<<<dim3(96, 16), cblk>>>(w_spr,  512,  1024, 1024, 3072, wb_spr);
    split_rows<<<dim3(4, TSTEPS * BATCH), 256>>>(observations, sb_obs, 1024);
    split_rows<<<dim3(4, BATCH), 256>>>(prev_belief, sb_belief, 1024);
    split_state0<<<512, 256>>>(prev_state, sb_state);

    // ---- GEMM params:               A0        A1        Wb       bias    C      K1    K2    L     Kp    ldc   partStride
    GemmP pes  = { sb_state,  nullptr, wb_es,   b_es,   hid_p, 512,  0,    512,  1536, 1024, 512 * 1024 };
    GemmP pgi  = { sb_hidden, nullptr, wb_ih,   b_ih,   gi,    1024, 0,    1024, 3072, 3072, 512 * 3072 };
    GemmP pgh  = { sb_belief, nullptr, wb_hh,   b_hh,   gh,    1024, 0,    1024, 3072, 3072, 512 * 3072 };
    GemmP pep  = { sb_belief, nullptr, wb_ebpo, b_ebpo, hp_p,  1024, 1024, 2048, 6144, 1024, 512 * 1024 };
    GemmP peq  = { sb_belief, sb_pose, wb_ebpr, b_ebpr, hq_p,  1024, 64,   1088, 3264, 1024, 512 * 1024 };
    GemmP pso  = { sb_hp,     nullptr, wb_spo,  b_spo,  ypo,   1024, 0,    1024, 3072, 512,  512 * 512 };
    GemmP psr  = { sb_hq,     nullptr, wb_spr,  b_spr,  ypr,   1024, 0,    1024, 3072, 512,  512 * 512 };

    for (int t = 0; t < TSTEPS; t++) {
        const float* belief_p = (t == 0) ? prev_belief : out_belief + (size_t)(t - 1) * BATCH * BELIEF;
        float* belief_t = out_belief + (size_t)t * BATCH * BELIEF;
        const float* pose_t = poses + (size_t)t * BATCH * 6;
        pep.A1 = sb_obs + (size_t)t * BATCH * 3072;

        gemm_mma<64, 4><<<dim3(8, 8, 4), 256, SM64>>>(pes, pes);
        rrs1<<<2048, 256>>>(hid_p, sb_hidden, 4);
        gemm_mma<128, 3><<<dim3(24, 4, 6), 256, SM128>>>(pgi, pgh);
        gru_gate<<<2048, 256>>>(gi, gh, belief_p, pose_t, belief_t, sb_belief, sb_pose);
        gemm_mma<64, 2><<<dim3(8, 8, 4), 256, SM64>>>(pep, peq);
        rrs2<<<4096, 256>>>(hp_p, hq_p, sb_hp, sb_hq);
        gemm_mma<64, 4><<<dim3(4, 8, 8), 256, SM64>>>(pso, psr);
        dist_head2<<<1024, 256>>>(ypo, ypr,
                                  post_noise + (size_t)t * BATCH * STATE,
                                  prior_noise + (size_t)t * BATCH * STATE,
                                  out_pm  + (size_t)t * BATCH * STATE,
                                  out_psd + (size_t)t * BATCH * STATE,
                                  out_ps  + (size_t)t * BATCH * STATE,
                                  out_prm  + (size_t)t * BATCH * STATE,
                                  out_prsd + (size_t)t * BATCH * STATE,
                                  out_prs  + (size_t)t * BATCH * STATE,
                                  sb_state);
    }
}

// round 16
// speedup vs baseline: 1.1672x; 1.0184x over previous
#include <cuda_runtime.h>
#include <cuda_bf16.h>
#include <stdint.h>
#include <math.h>

#define BATCH 512
#define TSTEPS 32
#define BELIEF 1024
#define STATE 256
#define HIDDEN 1024
#define EMB 1024

#define BK 64
#define BN 128
#define APAD 72
#define ROWB (APAD * 2)
#define NSTAGE 3

// ---------------- scratch ----------------------------------------------------
__device__ float g_gi[3 * BATCH * 3 * BELIEF];
__device__ float g_gh[3 * BATCH * 3 * BELIEF];
__device__ float g_hid_p[3 * BATCH * BELIEF];
__device__ float g_hp_p[4 * BATCH * HIDDEN];
__device__ float g_hq_p[4 * BATCH * HIDDEN];
__device__ float g_ypo[4 * BATCH * 2 * STATE];
__device__ float g_ypr[4 * BATCH * 2 * STATE];

// split-bf16 activations: [R, 3L], sections [hi | lo | hi]
__device__ __align__(256) __nv_bfloat16 g_sb_state[BATCH * 3 * 512];
__device__ __align__(256) __nv_bfloat16 g_sb_hidden[BATCH * 3 * 1024];
__device__ __align__(256) __nv_bfloat16 g_sb_belief[BATCH * 3 * 1024];
__device__ __align__(256) __nv_bfloat16 g_sb_pose[BATCH * 3 * 64];
__device__ __align__(256) __nv_bfloat16 g_sb_hp[BATCH * 3 * 1024];
__device__ __align__(256) __nv_bfloat16 g_sb_hq[BATCH * 3 * 1024];
__device__ __align__(256) __nv_bfloat16 g_sb_obs[(size_t)TSTEPS * BATCH * 3 * 1024];

// split-bf16 weights [N, Kp=3L], sections [hi | hi | lo]
__device__ __align__(256) __nv_bfloat16 g_wb_es[1024 * 1536];
__device__ __align__(256) __nv_bfloat16 g_wb_ih[3072 * 3072];
__device__ __align__(256) __nv_bfloat16 g_wb_hh[3072 * 3072];
__device__ __align__(256) __nv_bfloat16 g_wb_ebpo[1024 * 6144];
__device__ __align__(256) __nv_bfloat16 g_wb_ebpr[1024 * 3264];
__device__ __align__(256) __nv_bfloat16 g_wb_spo[512 * 3072];
__device__ __align__(256) __nv_bfloat16 g_wb_spr[512 * 3072];

// ---------------- helpers ----------------------------------------------------
__device__ __forceinline__ uint32_t smem_u32(const void* p) {
    uint32_t a;
    asm("{ .reg .u64 t; cvta.to.shared.u64 t, %1; cvt.u32.u64 %0, t; }" : "=r"(a) : "l"(p));
    return a;
}
__device__ __forceinline__ void mma_bf16(float* c, const uint32_t* a, uint32_t b0, uint32_t b1) {
    asm volatile("mma.sync.aligned.m16n8k16.row.col.f32.bf16.bf16.f32 "
        "{%0,%1,%2,%3}, {%4,%5,%6,%7}, {%8,%9}, {%0,%1,%2,%3};"
        : "+f"(c[0]), "+f"(c[1]), "+f"(c[2]), "+f"(c[3])
        : "r"(a[0]), "r"(a[1]), "r"(a[2]), "r"(a[3]), "r"(b0), "r"(b1));
}

struct GemmP {
    const __nv_bfloat16* A0;
    const __nv_bfloat16* A1;
    const __nv_bfloat16* Wb;
    const float* bias;
    float* C;                       // partial base; split s writes C + s*partStride
    int K1, K2, L, Kp, ldc, partStride;
};

// ---------------- tensor-core GEMM (pure f32-partial, split-K') --------------
// blockIdx.z = gemm_idx * SPLITS + split_idx
template <int BMT, int SPLITS>
__global__ __launch_bounds__(256, 2) void gemm_mma(GemmP p0, GemmP p1)
{
    constexpr int MF = BMT / 64;
    constexpr int ASZ = BMT * ROWB;
    constexpr int BSZ = BN * ROWB;
    extern __shared__ char smem[];
    const int z = blockIdx.z;
    const int gidx = z / SPLITS, sidx = z % SPLITS;
    const GemmP p = gidx ? p1 : p0;
    const int nkt_all = p.Kp / BK;
    const int nbase = nkt_all / SPLITS, nrem = nkt_all % SPLITS;
    const int nkt = nbase + (sidx < nrem);
    const int kb = sidx * nbase + min(sidx, nrem);
    float* Cout = p.C + (size_t)sidx * p.partStride;
    const bool addBias = (sidx == 0);

    const int tid = threadIdx.x;
    const int wid = tid >> 5, lane = tid & 31;
    const int row0 = blockIdx.y * BMT, col0 = blockIdx.x * BN;
    const uint32_t sbase = smem_u32(smem);

    auto issue = [&](int i, int slot) {
        const int kp = i * BK;
        const int sec = (kp >= p.L) + (kp >= 2 * p.L);
        const int rb = kp - sec * p.L;
        const bool useA0 = (rb < p.K1);
        const __nv_bfloat16* abase = useA0
            ? (p.A0 + (size_t)row0 * (3 * p.K1) + sec * p.K1 + rb)
            : (p.A1 + (size_t)row0 * (3 * p.K2) + sec * p.K2 + (rb - p.K1));
        const int astr = useA0 ? 3 * p.K1 : 3 * p.K2;
        const uint32_t da = sbase + slot * ASZ;
        #pragma unroll
        for (int q = 0; q < BMT * 8 / 256; q++) {
            int idx = tid + q * 256;
            int r = idx >> 3, c = idx & 7;
            asm volatile("cp.async.cg.shared.global [%0], [%1], 16;"
                :: "r"(da + r * ROWB + c * 16), "l"(abase + (size_t)r * astr + c * 8));
        }
        const __nv_bfloat16* bbase = p.Wb + (size_t)col0 * p.Kp + i * BK;
        const uint32_t db = sbase + NSTAGE * ASZ + slot * BSZ;
        #pragma unroll
        for (int q = 0; q < BN * 8 / 256; q++) {
            int idx = tid + q * 256;
            int r = idx >> 3, c = idx & 7;
            asm volatile("cp.async.cg.shared.global [%0], [%1], 16;"
                :: "r"(db + r * ROWB + c * 16), "l"(bbase + (size_t)r * p.Kp + c * 8));
        }
        asm volatile("cp.async.commit_group;" ::: "memory");
    };

    const int wm = wid & 3, wn = wid >> 2;
    const uint32_t lrow = lane & 15;
    const uint32_t lk16 = (lane >> 4) * 16;

    float acc[MF][8][4];
    #pragma unroll
    for (int mf = 0; mf < MF; mf++)
        #pragma unroll
        for (int j = 0; j < 8; j++)
            #pragma unroll
            for (int q = 0; q < 4; q++) acc[mf][j][q] = 0.f;

    issue(kb + 0, 0);
    issue(kb + 1, 1);

    for (int it = 0; it < nkt; it++) {
        asm volatile("cp.async.wait_group 1;" ::: "memory");
        __syncthreads();
        const int slot = it % NSTAGE;
        const uint32_t aS = sbase + slot * ASZ + (wm * 16 * MF + lrow) * ROWB + lk16;
        const uint32_t bS = sbase + NSTAGE * ASZ + slot * BSZ + (wn * 64 + lrow) * ROWB + lk16;
        #pragma unroll
        for (int ks = 0; ks < 4; ks++) {
            uint32_t a[MF][4];
            #pragma unroll
            for (int mf = 0; mf < MF; mf++)
                asm volatile("ldmatrix.sync.aligned.m8n8.x4.shared.b16 {%0,%1,%2,%3}, [%4];"
                    : "=r"(a[mf][0]), "=r"(a[mf][1]), "=r"(a[mf][2]), "=r"(a[mf][3])
                    : "r"(aS + mf * 16 * ROWB + ks * 32));
            #pragma unroll
            for (int nb = 0; nb < 4; nb++) {
                uint32_t b[4];
                asm volatile("ldmatrix.sync.aligned.m8n8.x4.shared.b16 {%0,%1,%2,%3}, [%4];"
                    : "=r"(b[0]), "=r"(b[1]), "=r"(b[2]), "=r"(b[3])
                    : "r"(bS + nb * 16 * ROWB + ks * 32));
                #pragma unroll
                for (int mf = 0; mf < MF; mf++) {
                    mma_bf16(acc[mf][2 * nb + 0], a[mf], b[0], b[2]);
                    mma_bf16(acc[mf][2 * nb + 1], a[mf], b[1], b[3]);
                }
            }
        }
        if (it + 2 < nkt) issue(kb + it + 2, (it + 2) % NSTAGE);
        else asm volatile("cp.async.commit_group;" ::: "memory");
    }

    #pragma unroll
    for (int mf = 0; mf < MF; mf++) {
        #pragma unroll
        for (int nf = 0; nf < 8; nf++) {
            const int row_ = row0 + wm * 16 * MF + mf * 16 + (lane >> 2);
            const int col_ = col0 + wn * 64 + nf * 8 + (lane & 3) * 2;
            const float b0 = addBias ? p.bias[col_] : 0.f;
            const float b1 = addBias ? p.bias[col_ + 1] : 0.f;
            #pragma unroll
            for (int rh = 0; rh < 2; rh++) {
                float v0 = acc[mf][nf][rh * 2 + 0] + b0;
                float v1 = acc[mf][nf][rh * 2 + 1] + b1;
                const int rr = row_ + rh * 8;
                *reinterpret_cast<float2*>(&Cout[(size_t)rr * p.ldc + col_]) = make_float2(v0, v1);
            }
        }
    }
}

// ---------------- weight conversion -----------------------------------------
__global__ void convert_w(const float* __restrict__ W, int N, int Keff, int L,
                          int Kp, __nv_bfloat16* __restrict__ out)
{
    __shared__ unsigned short tile[32][33];
    int k0 = blockIdx.x * 32, n0 = blockIdx.y * 32;
    int tx = threadIdx.x, ty = threadIdx.y;
    #pragma unroll
    for (int q = 0; q < 4; q++) {
        int kl = ty + q * 8;
        int kp = k0 + kl;
        int s = kp / L;
        int rr = kp - s * L;
        float v = (rr < Keff) ? W[(size_t)rr * N + n0 + tx] : 0.f;
        __nv_bfloat16 b;
        if (s == 2) {
            __nv_bfloat16 h = __float2bfloat16(v);
            b = __float2bfloat16(v - __bfloat162float(h));
        } else b = __float2bfloat16(v);
        tile[kl][tx] = __bfloat16_as_ushort(b);
    }
    __syncthreads();
    #pragma unroll
    for (int q = 0; q < 4; q++) {
        int nl = ty + q * 8;
        reinterpret_cast<unsigned short*>(out)[(size_t)(n0 + nl) * Kp + k0 + tx] = tile[tx][nl];
    }
}

// ---------------- activation splits ------------------------------------------
__global__ void split_rows(const float* __restrict__ src, __nv_bfloat16* __restrict__ dst, int L)
{
    int r = blockIdx.y;
    int c = blockIdx.x * 256 + threadIdx.x;
    float v = src[(size_t)r * L + c];
    __nv_bfloat16 h = __float2bfloat16(v);
    __nv_bfloat16 l = __float2bfloat16(v - __bfloat162float(h));
    size_t o = (size_t)r * 3 * L + c;
    dst[o] = h; dst[o + L] = l; dst[o + 2 * L] = h;
}
__global__ void split_state0(const float* __restrict__ ps, __nv_bfloat16* __restrict__ dst)
{
    int idx = blockIdx.x * 256 + threadIdx.x;
    int b = idx >> 8, c = idx & 255;
    float v = ps[idx];
    __nv_bfloat16 h = __float2bfloat16(v);
    __nv_bfloat16 l = __float2bfloat16(v - __bfloat162float(h));
    size_t base = (size_t)b * 1536;
    dst[base + c] = h;        dst[base + 256 + c] = h;
    dst[base + 512 + c] = l;  dst[base + 768 + c] = l;
    dst[base + 1024 + c] = h; dst[base + 1280 + c] = h;
}

// ---------------- reduce + relu + split --------------------------------------
__global__ void rrs1(const float* __restrict__ part, __nv_bfloat16* __restrict__ dst, int nsplit)
{
    int idx = blockIdx.x * 256 + threadIdx.x;          // 512*1024
    int r = idx >> 10, c = idx & 1023;
    float v = 0.f;
    for (int s = 0; s < nsplit; s++) v += part[idx + (size_t)s * 512 * 1024];
    v = fmaxf(v, 0.f);
    __nv_bfloat16 h = __float2bfloat16(v);
    __nv_bfloat16 l = __float2bfloat16(v - __bfloat162float(h));
    size_t o = (size_t)r * 3072 + c;
    dst[o] = h; dst[o + 1024] = l; dst[o + 2048] = h;
}
__global__ void rrs2(const float* __restrict__ pa, const float* __restrict__ pb,
                     __nv_bfloat16* __restrict__ da, __nv_bfloat16* __restrict__ db,
                     int na, int nb)
{
    int i2 = blockIdx.x * 256 + threadIdx.x;           // 2*512*1024
    int half = i2 >> 19;
    int idx = i2 & 524287;
    const float* part = half ? pb : pa;
    __nv_bfloat16* dst = half ? db : da;
    int ns = half ? nb : na;
    int r = idx >> 10, c = idx & 1023;
    float v = 0.f;
    for (int s = 0; s < ns; s++) v += part[idx + (size_t)s * 512 * 1024];
    v = fmaxf(v, 0.f);
    __nv_bfloat16 h = __float2bfloat16(v);
    __nv_bfloat16 l = __float2bfloat16(v - __bfloat162float(h));
    size_t o = (size_t)r * 3072 + c;
    dst[o] = h; dst[o + 1024] = l; dst[o + 2048] = h;
}

// ---------------- GRU gate (gi: 3 partials, gh: 3 partials) -----------------
__device__ __forceinline__ float sigmoidf_(float x) { return 1.f / (1.f + expf(-x)); }
#define PS3 (512 * 3072)

__global__ void gru_gate(const float* __restrict__ gi, const float* __restrict__ gh,
                         const float* __restrict__ hprev, const float* __restrict__ pose_t,
                         float* __restrict__ belief_out,
                         __nv_bfloat16* __restrict__ sb_belief,
                         __nv_bfloat16* __restrict__ sb_pose)
{
    int idx = blockIdx.x * blockDim.x + threadIdx.x;
    int b = idx >> 10;
    int j = idx & 1023;
    size_t base = (size_t)b * 3072;
    float ir = gi[base + j] + gi[PS3 + base + j] + gi[2 * PS3 + base + j];
    float iz = gi[base + 1024 + j] + gi[PS3 + base + 1024 + j] + gi[2 * PS3 + base + 1024 + j];
    float in_ = gi[base + 2048 + j] + gi[PS3 + base + 2048 + j] + gi[2 * PS3 + base + 2048 + j];
    float hr = gh[base + j] + gh[PS3 + base + j] + gh[2 * PS3 + base + j];
    float hz = gh[base + 1024 + j] + gh[PS3 + base + 1024 + j] + gh[2 * PS3 + base + 1024 + j];
    float hn = gh[base + 2048 + j] + gh[PS3 + base + 2048 + j] + gh[2 * PS3 + base + 2048 + j];
    float rg = sigmoidf_(ir + hr);
    float zg = sigmoidf_(iz + hz);
    float n = tanhf(in_ + rg * hn);
    float h = hprev[(size_t)b * 1024 + j];
    float hv = (1.f - zg) * n + zg * h;
    belief_out[(size_t)b * 1024 + j] = hv;
    __nv_bfloat16 bh = __float2bfloat16(hv);
    __nv_bfloat16 bl = __float2bfloat16(hv - __bfloat162float(bh));
    sb_belief[base + j] = bh;
    sb_belief[base + 1024 + j] = bl;
    sb_belief[base + 2048 + j] = bh;
    if (j < 6) {
        float pv = pose_t[b * 6 + j];
        __nv_bfloat16 ph = __float2bfloat16(pv);
        __nv_bfloat16 pl = __float2bfloat16(pv - __bfloat162float(ph));
        size_t pb = (size_t)b * 192;
        sb_pose[pb + j] = ph;
        sb_pose[pb + 64 + j] = pl;
        sb_pose[pb + 128 + j] = ph;
    }
}

// ---------------- merged dist heads (sums 4 split-K partials) ----------------
#define PSH (512 * 512)
__global__ void dist_head2(const float* __restrict__ ypo, const float* __restrict__ ypr,
                           const float* __restrict__ pn, const float* __restrict__ rn,
                           float* __restrict__ pm, float* __restrict__ psd, float* __restrict__ ps,
                           float* __restrict__ prm, float* __restrict__ prsd, float* __restrict__ prs,
                           __nv_bfloat16* __restrict__ sb_state)
{
    int i2 = blockIdx.x * 256 + threadIdx.x;
    int half = i2 >> 17;
    int idx = i2 & 131071;
    int b = idx >> 8, c = idx & 255;
    const float* y = half ? ypr : ypo;
    const float* nz = half ? rn : pn;
    size_t bm = (size_t)b * 512 + c;
    size_t br = bm + 256;
    float m = y[bm] + y[PSH + bm] + y[2 * PSH + bm] + y[3 * PSH + bm];
    float raw = y[br] + y[PSH + br] + y[2 * PSH + br] + y[3 * PSH + br];
    float sd = fmaxf(raw, 0.f) + log1pf(expf(-fabsf(raw))) + 0.1f;
    float st = m + sd * nz[idx];
    if (half) { prm[idx] = m; prsd[idx] = sd; prs[idx] = st; }
    else      { pm[idx] = m;  psd[idx] = sd;  ps[idx] = st; }
    __nv_bfloat16 h = __float2bfloat16(st);
    __nv_bfloat16 l = __float2bfloat16(st - __bfloat162float(h));
    int off = half ? 256 : 0;
    size_t base = (size_t)b * 1536 + off + c;
    sb_state[base] = h;
    sb_state[base + 512] = l;
    sb_state[base + 1024] = h;
}

// ---------------- launch ------------------------------------------------------
extern "C" void kernel_launch(void* const* d_in, const int* in_sizes, int n_in,
                              void* d_out, int out_size)
{
    const float* prev_state   = (const float*)d_in[0];
    const float* prev_belief  = (const float*)d_in[1];
    const float* poses        = (const float*)d_in[2];
    const float* observations = (const float*)d_in[3];
    const float* post_noise   = (const float*)d_in[4];
    const float* prior_noise  = (const float*)d_in[5];
    const float* w_es   = (const float*)d_in[6];
    const float* b_es   = (const float*)d_in[7];
    const float* w_ih   = (const float*)d_in[8];
    const float* w_hh   = (const float*)d_in[9];
    const float* b_ih   = (const float*)d_in[10];
    const float* b_hh   = (const float*)d_in[11];
    const float* w_ebpo = (const float*)d_in[12];
    const float* b_ebpo = (const float*)d_in[13];
    const float* w_spo  = (const float*)d_in[14];
    const float* b_spo  = (const float*)d_in[15];
    const float* w_ebpr = (const float*)d_in[16];
    const float* b_ebpr = (const float*)d_in[17];
    const float* w_spr  = (const float*)d_in[18];
    const float* b_spr  = (const float*)d_in[19];

    float* out = (float*)d_out;
    const size_t SZB = (size_t)TSTEPS * BATCH * BELIEF;
    const size_t SZS = (size_t)TSTEPS * BATCH * STATE;
    float* out_belief = out;
    float* out_prs  = out + SZB;
    float* out_prm  = out + SZB + 1 * SZS;
    float* out_prsd = out + SZB + 2 * SZS;
    float* out_ps   = out + SZB + 3 * SZS;
    float* out_pm   = out + SZB + 4 * SZS;
    float* out_psd  = out + SZB + 5 * SZS;

    float *gi, *gh, *hid_p, *hp_p, *hq_p, *ypo, *ypr;
    cudaGetSymbolAddress((void**)&gi, g_gi);
    cudaGetSymbolAddress((void**)&gh, g_gh);
    cudaGetSymbolAddress((void**)&hid_p, g_hid_p);
    cudaGetSymbolAddress((void**)&hp_p, g_hp_p);
    cudaGetSymbolAddress((void**)&hq_p, g_hq_p);
    cudaGetSymbolAddress((void**)&ypo, g_ypo);
    cudaGetSymbolAddress((void**)&ypr, g_ypr);

    __nv_bfloat16 *sb_state, *sb_hidden, *sb_belief, *sb_pose, *sb_hp, *sb_hq, *sb_obs;
    cudaGetSymbolAddress((void**)&sb_state, g_sb_state);
    cudaGetSymbolAddress((void**)&sb_hidden, g_sb_hidden);
    cudaGetSymbolAddress((void**)&sb_belief, g_sb_belief);
    cudaGetSymbolAddress((void**)&sb_pose, g_sb_pose);
    cudaGetSymbolAddress((void**)&sb_hp, g_sb_hp);
    cudaGetSymbolAddress((void**)&sb_hq, g_sb_hq);
    cudaGetSymbolAddress((void**)&sb_obs, g_sb_obs);

    __nv_bfloat16 *wb_es, *wb_ih, *wb_hh, *wb_ebpo, *wb_ebpr, *wb_spo, *wb_spr;
    cudaGetSymbolAddress((void**)&wb_es, g_wb_es);
    cudaGetSymbolAddress((void**)&wb_ih, g_wb_ih);
    cudaGetSymbolAddress((void**)&wb_hh, g_wb_hh);
    cudaGetSymbolAddress((void**)&wb_ebpo, g_wb_ebpo);
    cudaGetSymbolAddress((void**)&wb_ebpr, g_wb_ebpr);
    cudaGetSymbolAddress((void**)&wb_spo, g_wb_spo);
    cudaGetSymbolAddress((void**)&wb_spr, g_wb_spr);

    const int SM128 = NSTAGE * (128 + BN) * ROWB;   // 110592
    cudaFuncSetAttribute((const void*)gemm_mma<128, 3>,
                         cudaFuncAttributeMaxDynamicSharedMemorySize, SM128);
    cudaFuncSetAttribute((const void*)gemm_mma<128, 4>,
                         cudaFuncAttributeMaxDynamicSharedMemorySize, SM128);

    // ---- upfront conversions ----
    dim3 cblk(32, 8);
    convert_w<<<dim3(48, 32), cblk>>>(w_es,   1024, 512,  512,  1536, wb_es);
    convert_w<<<dim3(96, 96), cblk>>>(w_ih,   3072, 1024, 1024, 3072, wb_ih);
    convert_w<<<dim3(96, 96), cblk>>>(w_hh,   3072, 1024, 1024, 3072, wb_hh);
    convert_w<<<dim3(192, 32), cblk>>>(w_ebpo, 1024, 2048, 2048, 6144, wb_ebpo);
    convert_w<<<dim3(102, 32), cblk>>>(w_ebpr, 1024, 1030, 1088, 3264, wb_ebpr);
    convert_w<<<dim3(96, 16), cblk>>>(w_spo,  512,  1024, 1024, 3072, wb_spo);
    convert_w<<<dim3(96, 16), cblk>>>(w_spr,  512,  1024, 1024, 3072, wb_spr);
    split_rows<<<dim3(4, TSTEPS * BATCH), 256>>>(observations, sb_obs, 1024);
    split_rows<<<dim3(4, BATCH), 256>>>(prev_belief, sb_belief, 1024);
    split_state0<<<512, 256>>>(prev_state, sb_state);

    // ---- GEMM params:               A0        A1        Wb       bias    C      K1    K2    L     Kp    ldc   partStride
    GemmP pes  = { sb_state,  nullptr, wb_es,   b_es,   hid_p, 512,  0,    512,  1536, 1024, 512 * 1024 };
    GemmP pgi  = { sb_hidden, nullptr, wb_ih,   b_ih,   gi,    1024, 0,    1024, 3072, 3072, 512 * 3072 };
    GemmP pgh  = { sb_belief, nullptr, wb_hh,   b_hh,   gh,    1024, 0,    1024, 3072, 3072, 512 * 3072 };
    GemmP pep  = { sb_belief, nullptr, wb_ebpo, b_ebpo, hp_p,  1024, 1024, 2048, 6144, 1024, 512 * 1024 };
    GemmP peq  = { sb_belief, sb_pose, wb_ebpr, b_ebpr, hq_p,  1024, 64,   1088, 3264, 1024, 512 * 1024 };
    GemmP pso  = { sb_hp,     nullptr, wb_spo,  b_spo,  ypo,   1024, 0,    1024, 3072, 512,  512 * 512 };
    GemmP psr  = { sb_hq,     nullptr, wb_spr,  b_spr,  ypr,   1024, 0,    1024, 3072, 512,  512 * 512 };

    for (int t = 0; t < TSTEPS; t++) {
        const float* belief_p = (t == 0) ? prev_belief : out_belief + (size_t)(t - 1) * BATCH * BELIEF;
        float* belief_t = out_belief + (size_t)t * BATCH * BELIEF;
        const float* pose_t = poses + (size_t)t * BATCH * 6;
        pep.A1 = sb_obs + (size_t)t * BATCH * 3072;

        gemm_mma<128, 3><<<dim3(8, 4, 3), 256, SM128>>>(pes, pes);
        rrs1<<<2048, 256>>>(hid_p, sb_hidden, 3);
        gemm_mma<128, 3><<<dim3(24, 4, 6), 256, SM128>>>(pgi, pgh);
        gru_gate<<<2048, 256>>>(gi, gh, belief_p, pose_t, belief_t, sb_belief, sb_pose);
        gemm_mma<128, 4><<<dim3(8, 4, 8), 256, SM128>>>(pep, peq);
        rrs2<<<4096, 256>>>(hp_p, hq_p, sb_hp, sb_hq, 4, 4);
        gemm_mma<128, 4><<<dim3(4, 4, 8), 256, SM128>>>(pso, psr);
        dist_head2<<<1024, 256>>>(ypo, ypr,
                                  post_noise + (size_t)t * BATCH * STATE,
                                  prior_noise + (size_t)t * BATCH * STATE,
                                  out_pm  + (size_t)t * BATCH * STATE,
                                  out_psd + (size_t)t * BATCH * STATE,
                                  out_ps  + (size_t)t * BATCH * STATE,
                                  out_prm  + (size_t)t * BATCH * STATE,
                                  out_prsd + (size_t)t * BATCH * STATE,
                                  out_prs  + (size_t)t * BATCH * STATE,
                                  sb_state);
    }
}